// round 7
// baseline (speedup 1.0000x reference)
#include <cuda_runtime.h>
#include <cstdint>

// Partitionable-threefry dropout (exact JAX match, rel_err = 0.0 confirmed):
//   bits[i] = fold(threefry2x32(key=(0,42), counter=(0,i))), fold = w0 ^ w1
//   keep    = bits < (7549747 << 9)
//   out[i]  = keep ? x[i] * (1/0.9) : 0,  cols [0,64) of each 4096-row -> 0
#define KS1 0x0000002Au
#define KS2 0x1BD11BF0u          // 0x1BD11BDA ^ 0 ^ 42

#define KEEP_CMP 0xE6666600u     // 7549747u << 9
#define DROP_SCALE ((float)(1.0 / 0.9))

__device__ __forceinline__ uint32_t rotl_shf(uint32_t x, int r) {
    return __funnelshift_l(x, x, r);   // SHF (alu pipe)
}

// Adds forced onto the fma pipe as IMAD (opaque multiplier `one` == 1).
__device__ __forceinline__ uint32_t fadd(uint32_t a, uint32_t b, uint32_t one) {
    uint32_t r;
    asm("mad.lo.u32 %0, %1, %2, %3;" : "=r"(r) : "r"(b), "r"(one), "r"(a));
    return r;
}
template <uint32_t C>
__device__ __forceinline__ uint32_t faddc(uint32_t a, uint32_t one) {
    uint32_t r;
    asm("mad.lo.u32 %0, %1, %2, %3;" : "=r"(r) : "r"(a), "r"(one), "n"(C));
    return r;
}

// Rotate via wide multiply on the fma pipe:
//   t = x * 2^R (IMAD.WIDE): t.lo = x<<R, t.hi = x>>(32-R), disjoint bits.
//   (t.lo | t.hi) ^ x0 fuses into ONE LOP3 (alu).
// Round cost: 2 fma + 1 alu (vs 1 fma + 2 alu for SHF form).
template <int R>
__device__ __forceinline__ uint32_t rot_xor_wide(uint32_t x1, uint32_t x0) {
    uint32_t lo, hi;
    asm("{\n\t"
        ".reg .u64 t;\n\t"
        "mul.wide.u32 t, %2, %3;\n\t"
        "mov.b64 {%0, %1}, t;\n\t"
        "}"
        : "=r"(lo), "=r"(hi) : "r"(x1), "n"(1u << R));
    return (lo | hi) ^ x0;
}

// Full threefry2x32 block, c0 = 0, c1 = i, key (0,42); returns w0 ^ w1.
// 13 rounds use SHF form (2 alu), 7 rounds use wide-mul form (1 alu) so the
// alu and fma pipes are balanced (~33 vs ~37 ops/element).
__device__ __forceinline__ uint32_t threefry_fold(uint32_t i, uint32_t one) {
    uint32_t x1 = faddc<KS1>(i, one);       // x1 = i + 42
    uint32_t x0 = x1;                       // round-1 add folds (x0 was 0)
    x1 = rot_xor_wide<13>(x1, x0);                              // r1  (B)

    x0 = fadd(x0, x1, one); x1 = rotl_shf(x1, 15) ^ x0;         // r2  (A)
    x0 = fadd(x0, x1, one); x1 = rotl_shf(x1, 26) ^ x0;         // r3  (A)
    x0 = fadd(x0, x1, one); x1 = rot_xor_wide<6>(x1, x0);       // r4  (B)
    x0 = faddc<KS1>(x0, one); x1 = faddc<KS2 + 1u>(x1, one);

    x0 = fadd(x0, x1, one); x1 = rotl_shf(x1, 17) ^ x0;         // r5  (A)
    x0 = fadd(x0, x1, one); x1 = rotl_shf(x1, 29) ^ x0;         // r6  (A)
    x0 = fadd(x0, x1, one); x1 = rotl_shf(x1, 16) ^ x0;         // r7  (A)
    x0 = fadd(x0, x1, one); x1 = rot_xor_wide<24>(x1, x0);      // r8  (B)
    x0 = faddc<KS2>(x0, one); x1 = faddc<2u>(x1, one);

    x0 = fadd(x0, x1, one); x1 = rotl_shf(x1, 13) ^ x0;         // r9  (A)
    x0 = fadd(x0, x1, one); x1 = rot_xor_wide<15>(x1, x0);      // r10 (B)
    x0 = fadd(x0, x1, one); x1 = rotl_shf(x1, 26) ^ x0;         // r11 (A)
    x0 = fadd(x0, x1, one); x1 = rot_xor_wide<6>(x1, x0);       // r12 (B)
    /* x0 += KS0 == 0: skipped */ x1 = faddc<KS1 + 3u>(x1, one);

    x0 = fadd(x0, x1, one); x1 = rotl_shf(x1, 17) ^ x0;         // r13 (A)
    x0 = fadd(x0, x1, one); x1 = rotl_shf(x1, 29) ^ x0;         // r14 (A)
    x0 = fadd(x0, x1, one); x1 = rotl_shf(x1, 16) ^ x0;         // r15 (A)
    x0 = fadd(x0, x1, one); x1 = rot_xor_wide<24>(x1, x0);      // r16 (B)
    x0 = faddc<KS1>(x0, one); x1 = faddc<KS2 + 4u>(x1, one);

    x0 = fadd(x0, x1, one); x1 = rotl_shf(x1, 13) ^ x0;         // r17 (A)
    x0 = fadd(x0, x1, one); x1 = rotl_shf(x1, 15) ^ x0;         // r18 (A)
    x0 = fadd(x0, x1, one); x1 = rotl_shf(x1, 26) ^ x0;         // r19 (A)
    x0 = fadd(x0, x1, one); x1 = rot_xor_wide<6>(x1, x0);       // r20 (B)
    x0 = faddc<KS2>(x0, one); x1 = faddc<5u>(x1, one);

    return x0 ^ x1;
}

// 8 consecutive elements per thread: two float4 loads/stores, 8 independent
// threefry chains for ILP. base is 8-aligned and 64 % 8 == 0, so the
// column-kill test (i & 4095) < 64 is uniform across the group.
//
// 128-thread blocks with min 8 blocks/SM: up to 64 regs/thread (vs 32 at
// 256x8) — room for the IMAD.WIDE register pairs without allocator thrash,
// while still holding 1024 threads/SM.
__global__ void __launch_bounds__(128, 8)
dropout_threefry_part_kernel(const float* __restrict__ x,
                             float* __restrict__ out,
                             uint32_t one) {
    uint32_t base = (blockIdx.x * blockDim.x + threadIdx.x) * 8u;

    const float4 a = *reinterpret_cast<const float4*>(x + base);
    const float4 b = *reinterpret_cast<const float4*>(x + base + 4u);

    const float scale = ((base & 4095u) < 64u) ? 0.0f : DROP_SCALE;

    uint32_t bits[8];
#pragma unroll
    for (int j = 0; j < 8; ++j) {
        bits[j] = threefry_fold(base + (uint32_t)j, one);
    }

    float4 ra, rb;
    ra.x = (bits[0] < KEEP_CMP) ? a.x * scale : 0.0f;
    ra.y = (bits[1] < KEEP_CMP) ? a.y * scale : 0.0f;
    ra.z = (bits[2] < KEEP_CMP) ? a.z * scale : 0.0f;
    ra.w = (bits[3] < KEEP_CMP) ? a.w * scale : 0.0f;
    rb.x = (bits[4] < KEEP_CMP) ? b.x * scale : 0.0f;
    rb.y = (bits[5] < KEEP_CMP) ? b.y * scale : 0.0f;
    rb.z = (bits[6] < KEEP_CMP) ? b.z * scale : 0.0f;
    rb.w = (bits[7] < KEEP_CMP) ? b.w * scale : 0.0f;

    *reinterpret_cast<float4*>(out + base) = ra;
    *reinterpret_cast<float4*>(out + base + 4u) = rb;
}

extern "C" void kernel_launch(void* const* d_in, const int* in_sizes, int n_in,
                              void* d_out, int out_size) {
    const float* x = (const float*)d_in[0];
    float* out = (float*)d_out;

    const uint32_t n = (uint32_t)out_size;   // 16384 * 4096 = 2^26
    const int threads = 128;
    const uint32_t elems_per_block = threads * 8u;
    const int blocks = (int)((n + elems_per_block - 1) / elems_per_block);

    dropout_threefry_part_kernel<<<blocks, threads>>>(x, out, 1u);
}

// round 8
// speedup vs baseline: 1.0891x; 1.0891x over previous
#include <cuda_runtime.h>
#include <cstdint>

// Partitionable-threefry dropout (exact JAX match, rel_err = 0.0 confirmed):
//   bits[i] = fold(threefry2x32(key=(0,42), counter=(0,i))), fold = w0 ^ w1
//   keep    = bits < (7549747 << 9)
//   out[i]  = keep ? x[i] * (1/0.9) : 0,  cols [0,64) of each 4096-row -> 0
#define KS1 0x0000002Au
#define KS2 0x1BD11BF0u          // 0x1BD11BDA ^ 0 ^ 42

#define KEEP_CMP 0xE6666600u     // 7549747u << 9
#define DROP_SCALE ((float)(1.0 / 0.9))

__device__ __forceinline__ uint32_t rotl_shf(uint32_t x, int r) {
    return __funnelshift_l(x, x, r);   // SHF (alu pipe)
}

// Adds forced onto the fma pipe as IMAD (opaque multiplier `one` == 1).
__device__ __forceinline__ uint32_t fadd(uint32_t a, uint32_t b, uint32_t one) {
    uint32_t r;
    asm("mad.lo.u32 %0, %1, %2, %3;" : "=r"(r) : "r"(b), "r"(one), "r"(a));
    return r;
}
template <uint32_t C>
__device__ __forceinline__ uint32_t faddc(uint32_t a, uint32_t one) {
    uint32_t r;
    asm("mad.lo.u32 %0, %1, %2, %3;" : "=r"(r) : "r"(a), "r"(one), "n"(C));
    return r;
}

// Rotate via wide multiply on the fma pipe:
//   t = x * 2^R (IMAD.WIDE): t.lo = x<<R, t.hi = x>>(32-R), disjoint bits.
//   (t.lo | t.hi) ^ x0 fuses into ONE LOP3 (alu).
// Used sparingly (4 of 20 rounds) to shave the alu pipe just below the
// issue bound without the register-pair pressure that sank the 7-wide try.
template <int R>
__device__ __forceinline__ uint32_t rot_xor_wide(uint32_t x1, uint32_t x0) {
    uint32_t lo, hi;
    asm("{\n\t"
        ".reg .u64 t;\n\t"
        "mul.wide.u32 t, %2, %3;\n\t"
        "mov.b64 {%0, %1}, t;\n\t"
        "}"
        : "=r"(lo), "=r"(hi) : "r"(x1), "n"(1u << R));
    return (lo | hi) ^ x0;
}

// Full threefry2x32 block, c0 = 0, c1 = i, key (0,42); returns w0 ^ w1.
// 16 SHF rounds (2 alu + 1 fma) + 4 wide rounds (1 alu + 2 fma):
// alu ~= 35/elem, fma ~= 38/elem, issue ~= 73/elem -> issue-bound.
__device__ __forceinline__ uint32_t threefry_fold(uint32_t i, uint32_t one) {
    uint32_t x1 = faddc<KS1>(i, one);       // x1 = i + 42
    uint32_t x0 = x1;                       // round-1 add folds (x0 was 0)
    x1 = rot_xor_wide<13>(x1, x0);                              // r1  (wide)

    x0 = fadd(x0, x1, one); x1 = rotl_shf(x1, 15) ^ x0;         // r2
    x0 = fadd(x0, x1, one); x1 = rotl_shf(x1, 26) ^ x0;         // r3
    x0 = fadd(x0, x1, one); x1 = rotl_shf(x1,  6) ^ x0;         // r4
    x0 = faddc<KS1>(x0, one); x1 = faddc<KS2 + 1u>(x1, one);

    x0 = fadd(x0, x1, one); x1 = rotl_shf(x1, 17) ^ x0;         // r5
    x0 = fadd(x0, x1, one); x1 = rotl_shf(x1, 29) ^ x0;         // r6
    x0 = fadd(x0, x1, one); x1 = rotl_shf(x1, 16) ^ x0;         // r7
    x0 = fadd(x0, x1, one); x1 = rot_xor_wide<24>(x1, x0);      // r8  (wide)
    x0 = faddc<KS2>(x0, one); x1 = faddc<2u>(x1, one);

    x0 = fadd(x0, x1, one); x1 = rotl_shf(x1, 13) ^ x0;         // r9
    x0 = fadd(x0, x1, one); x1 = rotl_shf(x1, 15) ^ x0;         // r10
    x0 = fadd(x0, x1, one); x1 = rotl_shf(x1, 26) ^ x0;         // r11
    x0 = fadd(x0, x1, one); x1 = rotl_shf(x1,  6) ^ x0;         // r12
    /* x0 += KS0 == 0: skipped */ x1 = faddc<KS1 + 3u>(x1, one);

    x0 = fadd(x0, x1, one); x1 = rotl_shf(x1, 17) ^ x0;         // r13
    x0 = fadd(x0, x1, one); x1 = rotl_shf(x1, 29) ^ x0;         // r14
    x0 = fadd(x0, x1, one); x1 = rotl_shf(x1, 16) ^ x0;         // r15
    x0 = fadd(x0, x1, one); x1 = rot_xor_wide<24>(x1, x0);      // r16 (wide)
    x0 = faddc<KS1>(x0, one); x1 = faddc<KS2 + 4u>(x1, one);

    x0 = fadd(x0, x1, one); x1 = rotl_shf(x1, 13) ^ x0;         // r17
    x0 = fadd(x0, x1, one); x1 = rotl_shf(x1, 15) ^ x0;         // r18
    x0 = fadd(x0, x1, one); x1 = rotl_shf(x1, 26) ^ x0;         // r19
    x0 = fadd(x0, x1, one); x1 = rot_xor_wide<6>(x1, x0);       // r20 (wide)
    x0 = faddc<KS2>(x0, one); x1 = faddc<5u>(x1, one);

    return x0 ^ x1;
}

// 8 consecutive elements per thread: two float4 loads/stores, 8 independent
// threefry chains for ILP. base is 8-aligned and 64 % 8 == 0, so the
// column-kill test (i & 4095) < 64 is uniform across the group.
__global__ void __launch_bounds__(256, 4)
dropout_threefry_part_kernel(const float* __restrict__ x,
                             float* __restrict__ out,
                             uint32_t one) {
    uint32_t base = (blockIdx.x * blockDim.x + threadIdx.x) * 8u;

    const float4 a = *reinterpret_cast<const float4*>(x + base);
    const float4 b = *reinterpret_cast<const float4*>(x + base + 4u);

    const float scale = ((base & 4095u) < 64u) ? 0.0f : DROP_SCALE;

    uint32_t bits[8];
#pragma unroll
    for (int j = 0; j < 8; ++j) {
        bits[j] = threefry_fold(base + (uint32_t)j, one);
    }

    // Predicated-multiply tail: ISETP + @p FMUL (no FSEL on the alu pipe).
    float va[8] = {a.x, a.y, a.z, a.w, b.x, b.y, b.z, b.w};
    float r[8];
#pragma unroll
    for (int j = 0; j < 8; ++j) {
        float v = 0.0f;
        if (bits[j] < KEEP_CMP) v = va[j] * scale;
        r[j] = v;
    }

    float4 ra, rb;
    ra.x = r[0]; ra.y = r[1]; ra.z = r[2]; ra.w = r[3];
    rb.x = r[4]; rb.y = r[5]; rb.z = r[6]; rb.w = r[7];

    *reinterpret_cast<float4*>(out + base) = ra;
    *reinterpret_cast<float4*>(out + base + 4u) = rb;
}

extern "C" void kernel_launch(void* const* d_in, const int* in_sizes, int n_in,
                              void* d_out, int out_size) {
    const float* x = (const float*)d_in[0];
    float* out = (float*)d_out;

    const uint32_t n = (uint32_t)out_size;   // 16384 * 4096 = 2^26
    const int threads = 256;
    const uint32_t elems_per_block = threads * 8u;
    const int blocks = (int)((n + elems_per_block - 1) / elems_per_block);

    dropout_threefry_part_kernel<<<blocks, threads>>>(x, out, 1u);
}